// round 14
// baseline (speedup 1.0000x reference)
#include <cuda_runtime.h>
#include <math.h>
#include <stdint.h>

#define NB 8
#define TT 8
#define CC 128
#define HH 64
#define WW 64
#define HW 4096

// ---------------- device scratch (no allocations allowed) ----------------
__device__ float g_M[NB * TT * CC];
__device__ int   g_imp[TT * CC];
__device__ float g_red[(size_t)NB * TT * 4 * HW];        // 4 MB
__device__ float g_gv[(size_t)NB * TT * CC * HW];        // 134 MB: gv = map[isel]*x

// ---------------- K1: M = mean_hw + max_hw ----------------
__global__ void k1_stats(const float* __restrict__ x) {
    int blk = blockIdx.x;
    const float* p = x + (size_t)blk * HW;
    float s = 0.f, m = -INFINITY;
    for (int i = threadIdx.x; i < HW; i += 128) {
        float v = p[i];
        s += v;
        m = fmaxf(m, v);
    }
    for (int o = 16; o; o >>= 1) {
        s += __shfl_down_sync(0xffffffffu, s, o);
        m = fmaxf(m, __shfl_down_sync(0xffffffffu, m, o));
    }
    __shared__ float ss[4], sm[4];
    int w = threadIdx.x >> 5, l = threadIdx.x & 31;
    if (l == 0) { ss[w] = s; sm[w] = m; }
    __syncthreads();
    if (threadIdx.x == 0) {
        float S = ss[0] + ss[1] + ss[2] + ss[3];
        float Mx = fmaxf(fmaxf(sm[0], sm[1]), fmaxf(sm[2], sm[3]));
        g_M[blk] = S * (1.f / (float)HW) + Mx;
    }
}

// ---------------- K3F: topk mask (per-block recompute) + masked channel reductions ----------------
__global__ void k3f_reduce(const float* __restrict__ x) {
    int nt = blockIdx.y;           // n*8+t
    int t = nt & 7;
    int tid = threadIdx.x;         // 1024 threads
    __shared__ float sM[NB * TT * CC];
    __shared__ int simp[CC];
    for (int i = tid; i < NB * TT * CC; i += 1024) sM[i] = g_M[i];
    __syncthreads();
    if (tid < CC) {
        int c = tid;
        int mch = 0, mtm = 0;
        for (int n = 0; n < NB; n++) {
            const float* row = &sM[(n * TT + t) * CC];
            float v = row[c];
            int cnt = 0;
            for (int c2 = 0; c2 < CC; c2++) {
                float u = row[c2];
                cnt += (u > v) || (u == v && c2 < c);
            }
            if (cnt < 64) mch = 1;
            int cntt = 0;
            for (int t2 = 0; t2 < TT; t2++) {
                float u = sM[(n * TT + t2) * CC + c];
                cntt += (u > v) || (u == v && t2 < t);
            }
            if (cntt < 4) mtm = 1;
        }
        int ip = mch ^ mtm;
        simp[c] = ip;
        g_imp[t * CC + c] = ip;   // duplicate writes across blocks: same value, benign
    }
    __syncthreads();

    int pix = blockIdx.x * 1024 + tid;   // grid.x = 4
    const float* p = x + (size_t)nt * CC * HW + pix;
    float s_all = 0.f, s_im = 0.f, mx_im = -INFINITY, mx_sub = -INFINITY;
#pragma unroll 4
    for (int c = 0; c < CC; c++) {
        float v = p[(size_t)c * HW];
        int ip = simp[c];
        float vi = ip ? v : 0.f;
        float vs = ip ? 0.f : v;
        s_all += v;
        s_im += vi;
        mx_im = fmaxf(mx_im, vi);
        mx_sub = fmaxf(mx_sub, vs);
    }
    float* r = g_red + (size_t)nt * 4 * HW + pix;
    r[0]          = s_im * (1.f / 64.f);
    r[HW]         = mx_im;
    r[2 * HW]     = (s_all - s_im) * (1.f / 64.f);
    r[3 * HW]     = mx_sub;
}

// ---------------- K4F: maps conv+sigmoid fused with gv = map*x ----------------
__global__ void k4f_gv(const float* __restrict__ x,
                       const float* __restrict__ w1, const float* __restrict__ w2) {
    int nt = blockIdx.y; int t = nt & 7;
    int pix = blockIdx.x * 256 + threadIdx.x;
    int y = pix >> 6, xq = pix & 63;
    __shared__ float sw1[18], sw2[18];
    __shared__ int simp[CC];
    if (threadIdx.x < 18) { sw1[threadIdx.x] = w1[threadIdx.x]; sw2[threadIdx.x] = w2[threadIdx.x]; }
    for (int i = threadIdx.x; i < CC; i += 256) simp[i] = g_imp[t * CC + i];
    __syncthreads();
    const float* r = g_red + (size_t)nt * 4 * HW;
    float a_im = 0.f, a_sub = 0.f;
#pragma unroll
    for (int kh = 0; kh < 3; kh++) {
        int gy = y + kh - 1;
        if (gy < 0 || gy >= HH) continue;
#pragma unroll
        for (int kw = 0; kw < 3; kw++) {
            int gx = xq + kw - 1;
            if (gx < 0 || gx >= WW) continue;
            int o = gy * WW + gx;
            a_im  += sw1[kh * 3 + kw] * r[o]          + sw1[9 + kh * 3 + kw] * r[HW + o];
            a_sub += sw2[kh * 3 + kw] * r[2 * HW + o] + sw2[9 + kh * 3 + kw] * r[3 * HW + o];
        }
    }
    float im = 1.f / (1.f + expf(-a_im));
    float sb = 1.f / (1.f + expf(-a_sub));

    const float* xp = x + (size_t)nt * CC * HW + pix;
    float* gp = g_gv + (size_t)nt * CC * HW + pix;
#pragma unroll 4
    for (int dd = 0; dd < CC; dd++) {
        float xv = xp[(size_t)dd * HW];
        float mv = simp[dd] ? im : sb;
        gp[(size_t)dd * HW] = mv * xv;
    }
}

// ---------------- K5: 3D conv on gv, single-buffer, selected weights, 4 CTAs/SM ----------------
#define THY 32
#define THX 32
#define VROW 34
#define VCOL 40                    // [x0-4, x0+36) : 16B-aligned, halos free
#define PSZ (VROW * VCOL)          // 1360 floats per (t) plane
#define NCHK 10                    // float4 chunks per row

__device__ __forceinline__ unsigned long long pack2(float v) {
    unsigned long long r;
    asm("mov.b64 %0, {%1, %1};" : "=l"(r) : "f"(v));
    return r;
}
__device__ __forceinline__ void ffma2(unsigned long long& d, unsigned long long a, unsigned long long b) {
    asm("fma.rn.f32x2 %0, %1, %2, %0;" : "+l"(d) : "l"(a), "l"(b));
}
__device__ __forceinline__ void unpack2(unsigned long long v, float& lo, float& hi) {
    asm("mov.b64 {%0, %1}, %2;" : "=f"(lo), "=f"(hi) : "l"(v));
}
__device__ __forceinline__ void cp16(uint32_t dst, const void* src, bool ok) {
    int sz = ok ? 16 : 0;   // src-size 0 => full zero-fill
    asm volatile("cp.async.cg.shared.global [%0], [%1], 16, %2;" :: "r"(dst), "l"(src), "r"(sz));
}

extern __shared__ float smem5[];

__global__ void __launch_bounds__(256, 4) k5_conv(const float* __restrict__ wl,
                                                  float* __restrict__ out) {
    float* vs = smem5;               // 8 * PSZ floats (single buffer)
    float* ws = vs + 8 * PSZ;        // 1728 floats: selected weights [kd][t][k9][o]

    int n = blockIdx.z;
    int d = blockIdx.y;
    int tileid = blockIdx.x;
    int y0 = (tileid >> 1) * THY, x0 = (tileid & 1) * THX;
    int tid = threadIdx.x;

    uint32_t vs_u32;
    {
        uint32_t a;
        asm("{ .reg .u64 t; cvta.to.shared.u64 t, %1; cvt.u32.u64 %0, t; }" : "=r"(a) : "l"(vs));
        vs_u32 = a;
    }

    // per-CTA selected weight staging: ws[((kd*8+t)*9+k9)*8+o] = wl[(o*16+isel)*27 + kd*9 + k9]
    for (int i = tid; i < 1728; i += 256) {
        int o = i & 7; int q = i >> 3;              // q in [0,216)
        int k9 = q % 9; int s = q / 9;              // s in [0,24)
        int t = s & 7, kd = s >> 3;
        int dd = d + kd - 1;
        int isel = (dd >= 0 && dd < CC) ? (g_imp[t * CC + dd] ? t : t + 8) : 0;
        ws[i] = wl[(o * 16 + isel) * 27 + kd * 9 + k9];
    }

    int kds[3], np = 0;
#pragma unroll
    for (int kd = 0; kd < 3; kd++) {
        int dd = d + kd - 1;
        if (dd >= 0 && dd < CC) kds[np++] = kd;
    }

    const float* gvn = g_gv + (size_t)n * TT * CC * HW;  // + (t*CC+dd)*HW

    int lx = tid & 31;
    int tg = tid >> 5;

    unsigned long long acc[4][4];
#pragma unroll
    for (int pp = 0; pp < 4; pp++)
#pragma unroll
        for (int j = 0; j < 4; j++) acc[pp][j] = 0ull;

    for (int i = 0; i < np; i++) {
        int kd = kds[i];
        int dd = d + kd - 1;

        __syncthreads();   // vs free (prev compute done)

        // stage: 8 planes * 34 rows * 10 16B chunks = 2720 cp.async
        for (int e = tid; e < 8 * VROW * NCHK; e += 256) {
            int t = e / (VROW * NCHK);
            int rem = e - t * (VROW * NCHK);
            int row = rem / NCHK;
            int chunk = rem - row * NCHK;
            int gy = y0 + row - 1;
            int gxs = x0 - 4 + chunk * 4;           // 16B aligned
            bool ok = (gy >= 0 && gy < HH && gxs >= 0 && gxs + 4 <= WW);
            const float* gp = gvn + ((size_t)t * CC + dd) * HW;
            const float* src = ok ? (gp + gy * WW + gxs) : gp;
            cp16(vs_u32 + (uint32_t)((t * PSZ + row * VCOL + chunk * 4) * 4), src, ok);
        }
        asm volatile("cp.async.commit_group;");
        asm volatile("cp.async.wait_group 0;");
        __syncthreads();   // staged data + ws (on i==0) visible

        // compute contribution of this kd (weights pre-selected: linear (kd,t) index)
        const float* vbase = vs + (tg * 4) * VCOL + (lx + 3);
        const float* wkd = ws + kd * 8 * 72;
#pragma unroll 2
        for (int t = 0; t < 8; t++) {
            const float* wb = wkd + t * 72;
            const float* vb = vbase + t * PSZ;
#pragma unroll
            for (int kw = 0; kw < 3; kw++) {
                unsigned long long vp[6];
#pragma unroll
                for (int r = 0; r < 6; r++) vp[r] = pack2(vb[r * VCOL + kw]);
#pragma unroll
                for (int kh = 0; kh < 3; kh++) {
                    const ulonglong2* wq = (const ulonglong2*)(wb + (kh * 3 + kw) * 8);
                    ulonglong2 wA = wq[0], wB = wq[1];
#pragma unroll
                    for (int pp = 0; pp < 4; pp++) {
                        unsigned long long vv = vp[pp + kh];
                        ffma2(acc[pp][0], wA.x, vv);
                        ffma2(acc[pp][1], wA.y, vv);
                        ffma2(acc[pp][2], wB.x, vv);
                        ffma2(acc[pp][3], wB.y, vv);
                    }
                }
            }
        }
    }

    int px = x0 + lx;
#pragma unroll
    for (int pp = 0; pp < 4; pp++) {
        int py = y0 + tg * 4 + pp;
        size_t pb = (size_t)py * WW + px;
#pragma unroll
        for (int j = 0; j < 4; j++) {
            float lo, hi;
            unpack2(acc[pp][j], lo, hi);
            int o0 = 2 * j, o1 = 2 * j + 1;
            out[(((size_t)(n * 8 + o0)) * CC + d) * HW + pb] = lo;
            out[(((size_t)(n * 8 + o1)) * CC + d) * HW + pb] = hi;
        }
    }
}

// ---------------- launcher ----------------
extern "C" void kernel_launch(void* const* d_in, const int* in_sizes, int n_in,
                              void* d_out, int out_size) {
    const float* x  = (const float*)d_in[0];
    const float* w1 = (const float*)d_in[1];
    const float* w2 = (const float*)d_in[2];
    const float* wl = (const float*)d_in[3];
    float* out = (float*)d_out;

    k1_stats<<<NB * TT * CC, 128>>>(x);                    // launch 1
    { dim3 g(4, NB * TT);  k3f_reduce<<<g, 1024>>>(x); }   // launch 2
    { dim3 g(16, NB * TT); k4f_gv<<<g, 256>>>(x, w1, w2); }// launch 3
    {
        int smem = (8 * PSZ + 1728 + 16) * 4;              // ~50.4 KB -> 4 CTAs/SM
        cudaFuncSetAttribute(k5_conv, cudaFuncAttributeMaxDynamicSharedMemorySize, smem);
        dim3 g(4, CC, NB);
        k5_conv<<<g, 256, smem>>>(wl, out);                // launch 4 (ncu-captured slot)
    }
}

// round 16
// speedup vs baseline: 1.5375x; 1.5375x over previous
#include <cuda_runtime.h>
#include <math.h>
#include <stdint.h>

#define NB 8
#define TT 8
#define CC 128
#define HH 64
#define WW 64
#define HW 4096

// ---------------- device scratch (no allocations allowed) ----------------
__device__ float g_M[NB * TT * CC];
__device__ int   g_imp[TT * CC];
__device__ float g_red[(size_t)NB * TT * 4 * HW];        // 4 MB
__device__ float g_gv[(size_t)NB * TT * CC * HW];        // 134 MB: gv = map[isel]*x

// ---------------- K1: M = mean_hw + max_hw ----------------
__global__ void k1_stats(const float* __restrict__ x) {
    int blk = blockIdx.x;
    const float* p = x + (size_t)blk * HW;
    float s = 0.f, m = -INFINITY;
    for (int i = threadIdx.x; i < HW; i += 128) {
        float v = p[i];
        s += v;
        m = fmaxf(m, v);
    }
    for (int o = 16; o; o >>= 1) {
        s += __shfl_down_sync(0xffffffffu, s, o);
        m = fmaxf(m, __shfl_down_sync(0xffffffffu, m, o));
    }
    __shared__ float ss[4], sm[4];
    int w = threadIdx.x >> 5, l = threadIdx.x & 31;
    if (l == 0) { ss[w] = s; sm[w] = m; }
    __syncthreads();
    if (threadIdx.x == 0) {
        float S = ss[0] + ss[1] + ss[2] + ss[3];
        float Mx = fmaxf(fmaxf(sm[0], sm[1]), fmaxf(sm[2], sm[3]));
        g_M[blk] = S * (1.f / (float)HW) + Mx;
    }
}

// ---------------- K3F: topk mask (per-block recompute) + masked channel reductions ----------------
__global__ void k3f_reduce(const float* __restrict__ x) {
    int nt = blockIdx.y;           // n*8+t
    int t = nt & 7;
    int tid = threadIdx.x;         // 1024 threads
    __shared__ float sM[NB * TT * CC];
    __shared__ int simp[CC];
    for (int i = tid; i < NB * TT * CC; i += 1024) sM[i] = g_M[i];
    __syncthreads();
    if (tid < CC) {
        int c = tid;
        int mch = 0, mtm = 0;
        for (int n = 0; n < NB; n++) {
            const float* row = &sM[(n * TT + t) * CC];
            float v = row[c];
            int cnt = 0;
            for (int c2 = 0; c2 < CC; c2++) {
                float u = row[c2];
                cnt += (u > v) || (u == v && c2 < c);
            }
            if (cnt < 64) mch = 1;
            int cntt = 0;
            for (int t2 = 0; t2 < TT; t2++) {
                float u = sM[(n * TT + t2) * CC + c];
                cntt += (u > v) || (u == v && t2 < t);
            }
            if (cntt < 4) mtm = 1;
        }
        int ip = mch ^ mtm;
        simp[c] = ip;
        g_imp[t * CC + c] = ip;   // duplicate writes across blocks: same value, benign
    }
    __syncthreads();

    int pix = blockIdx.x * 1024 + tid;   // grid.x = 4
    const float* p = x + (size_t)nt * CC * HW + pix;
    float s_all = 0.f, s_im = 0.f, mx_im = -INFINITY, mx_sub = -INFINITY;
#pragma unroll 4
    for (int c = 0; c < CC; c++) {
        float v = p[(size_t)c * HW];
        int ip = simp[c];
        float vi = ip ? v : 0.f;
        float vs = ip ? 0.f : v;
        s_all += v;
        s_im += vi;
        mx_im = fmaxf(mx_im, vi);
        mx_sub = fmaxf(mx_sub, vs);
    }
    float* r = g_red + (size_t)nt * 4 * HW + pix;
    r[0]          = s_im * (1.f / 64.f);
    r[HW]         = mx_im;
    r[2 * HW]     = (s_all - s_im) * (1.f / 64.f);
    r[3 * HW]     = mx_sub;
}

// ---------------- K4F: maps conv+sigmoid fused with gv = map*x ----------------
__global__ void k4f_gv(const float* __restrict__ x,
                       const float* __restrict__ w1, const float* __restrict__ w2) {
    int nt = blockIdx.y; int t = nt & 7;
    int pix = blockIdx.x * 256 + threadIdx.x;
    int y = pix >> 6, xq = pix & 63;
    __shared__ float sw1[18], sw2[18];
    __shared__ int simp[CC];
    if (threadIdx.x < 18) { sw1[threadIdx.x] = w1[threadIdx.x]; sw2[threadIdx.x] = w2[threadIdx.x]; }
    for (int i = threadIdx.x; i < CC; i += 256) simp[i] = g_imp[t * CC + i];
    __syncthreads();
    const float* r = g_red + (size_t)nt * 4 * HW;
    float a_im = 0.f, a_sub = 0.f;
#pragma unroll
    for (int kh = 0; kh < 3; kh++) {
        int gy = y + kh - 1;
        if (gy < 0 || gy >= HH) continue;
#pragma unroll
        for (int kw = 0; kw < 3; kw++) {
            int gx = xq + kw - 1;
            if (gx < 0 || gx >= WW) continue;
            int o = gy * WW + gx;
            a_im  += sw1[kh * 3 + kw] * r[o]          + sw1[9 + kh * 3 + kw] * r[HW + o];
            a_sub += sw2[kh * 3 + kw] * r[2 * HW + o] + sw2[9 + kh * 3 + kw] * r[3 * HW + o];
        }
    }
    float im = 1.f / (1.f + expf(-a_im));
    float sb = 1.f / (1.f + expf(-a_sub));

    const float* xp = x + (size_t)nt * CC * HW + pix;
    float* gp = g_gv + (size_t)nt * CC * HW + pix;
#pragma unroll 4
    for (int dd = 0; dd < CC; dd++) {
        float xv = xp[(size_t)dd * HW];
        float mv = simp[dd] ? im : sb;
        gp[(size_t)dd * HW] = mv * xv;
    }
}

// ---------------- K5: 3D conv on gv, single-buffer, selected weights, 4 CTAs/SM ----------------
#define THY 32
#define THX 32
#define VROW 34
#define VCOL 40                    // [x0-4, x0+36) : 16B-aligned, halos free
#define PSZ (VROW * VCOL)          // 1360 floats per (t) plane
#define NCHK 10                    // float4 chunks per row

__device__ __forceinline__ unsigned long long pack2(float v) {
    unsigned long long r;
    asm("mov.b64 %0, {%1, %1};" : "=l"(r) : "f"(v));
    return r;
}
__device__ __forceinline__ void ffma2(unsigned long long& d, unsigned long long a, unsigned long long b) {
    asm("fma.rn.f32x2 %0, %1, %2, %0;" : "+l"(d) : "l"(a), "l"(b));
}
__device__ __forceinline__ void unpack2(unsigned long long v, float& lo, float& hi) {
    asm("mov.b64 {%0, %1}, %2;" : "=f"(lo), "=f"(hi) : "l"(v));
}
__device__ __forceinline__ void cp16(uint32_t dst, const void* src, bool ok) {
    int sz = ok ? 16 : 0;   // src-size 0 => full zero-fill
    asm volatile("cp.async.cg.shared.global [%0], [%1], 16, %2;" :: "r"(dst), "l"(src), "r"(sz));
}

extern __shared__ float smem5[];

__global__ void __launch_bounds__(256, 4) k5_conv(const float* __restrict__ wl,
                                                  float* __restrict__ out) {
    float* vs = smem5;               // 8 * PSZ floats (single buffer)
    float* ws = vs + 8 * PSZ;        // 1728 floats: selected weights [kd][t][k9][o]

    int n = blockIdx.z;
    int d = blockIdx.y;
    int tileid = blockIdx.x;
    int y0 = (tileid >> 1) * THY, x0 = (tileid & 1) * THX;
    int tid = threadIdx.x;

    uint32_t vs_u32;
    {
        uint32_t a;
        asm("{ .reg .u64 t; cvta.to.shared.u64 t, %1; cvt.u32.u64 %0, t; }" : "=r"(a) : "l"(vs));
        vs_u32 = a;
    }

    // per-CTA selected weight staging: ws[((kd*8+t)*9+k9)*8+o] = wl[(o*16+isel)*27 + kd*9 + k9]
    for (int i = tid; i < 1728; i += 256) {
        int o = i & 7; int q = i >> 3;              // q in [0,216)
        int k9 = q % 9; int s = q / 9;              // s in [0,24)
        int t = s & 7, kd = s >> 3;
        int dd = d + kd - 1;
        int isel = (dd >= 0 && dd < CC) ? (g_imp[t * CC + dd] ? t : t + 8) : 0;
        ws[i] = wl[(o * 16 + isel) * 27 + kd * 9 + k9];
    }

    int kds[3], np = 0;
#pragma unroll
    for (int kd = 0; kd < 3; kd++) {
        int dd = d + kd - 1;
        if (dd >= 0 && dd < CC) kds[np++] = kd;
    }

    const float* gvn = g_gv + (size_t)n * TT * CC * HW;  // + (t*CC+dd)*HW

    // ---- phase-invariant staging slots: each thread serves 2 of 340 (row,chunk) slots ----
    // slot 0: e = tid (always valid), slot 1: e = tid + 256 (valid if < 340)
    int soff0, goff0, soff1 = 0, goff1 = 0;
    bool ok0, ok1, in1;
    {
        int e = tid;
        int row = e / NCHK, ch = e - row * NCHK;
        int gy = y0 + row - 1, gxs = x0 - 4 + ch * 4;
        ok0 = (gy >= 0 && gy < HH && gxs >= 0 && gxs + 4 <= WW);
        goff0 = ok0 ? (gy * WW + gxs) : 0;
        soff0 = (row * VCOL + ch * 4) * 4;
        e = tid + 256;
        in1 = (e < VROW * NCHK);
        if (in1) {
            row = e / NCHK; ch = e - row * NCHK;
            gy = y0 + row - 1; gxs = x0 - 4 + ch * 4;
            ok1 = (gy >= 0 && gy < HH && gxs >= 0 && gxs + 4 <= WW);
            goff1 = ok1 ? (gy * WW + gxs) : 0;
            soff1 = (row * VCOL + ch * 4) * 4;
        } else ok1 = false;
    }

    int lx = tid & 31;
    int tg = tid >> 5;

    unsigned long long acc[4][4];
#pragma unroll
    for (int pp = 0; pp < 4; pp++)
#pragma unroll
        for (int j = 0; j < 4; j++) acc[pp][j] = 0ull;

    for (int i = 0; i < np; i++) {
        int kd = kds[i];
        int dd = d + kd - 1;

        __syncthreads();   // vs free (prev compute done)

        // stage: 8 planes x 2 slots per thread, all addresses precomputed
        const float* gp = gvn + (size_t)dd * HW;
#pragma unroll
        for (int t = 0; t < 8; t++) {
            const float* pb = gp + (size_t)t * CC * HW;
            uint32_t sb = vs_u32 + (uint32_t)(t * PSZ * 4);
            cp16(sb + soff0, pb + goff0, ok0);
            if (in1) cp16(sb + soff1, pb + goff1, ok1);
        }
        asm volatile("cp.async.commit_group;");
        asm volatile("cp.async.wait_group 0;");
        __syncthreads();   // staged data + ws (on i==0) visible

        // compute contribution of this kd (weights pre-selected: linear (kd,t) index)
        const float* vbase = vs + (tg * 4) * VCOL + (lx + 3);
        const float* wkd = ws + kd * 8 * 72;
        for (int t = 0; t < 8; t++) {
            const float* wb = wkd + t * 72;
            const float* vb = vbase + t * PSZ;
#pragma unroll
            for (int kw = 0; kw < 3; kw++) {
                unsigned long long vp[6];
#pragma unroll
                for (int r = 0; r < 6; r++) vp[r] = pack2(vb[r * VCOL + kw]);
#pragma unroll
                for (int kh = 0; kh < 3; kh++) {
                    const ulonglong2* wq = (const ulonglong2*)(wb + (kh * 3 + kw) * 8);
                    ulonglong2 wA = wq[0], wB = wq[1];
#pragma unroll
                    for (int pp = 0; pp < 4; pp++) {
                        unsigned long long vv = vp[pp + kh];
                        ffma2(acc[pp][0], wA.x, vv);
                        ffma2(acc[pp][1], wA.y, vv);
                        ffma2(acc[pp][2], wB.x, vv);
                        ffma2(acc[pp][3], wB.y, vv);
                    }
                }
            }
        }
    }

    int px = x0 + lx;
#pragma unroll
    for (int pp = 0; pp < 4; pp++) {
        int py = y0 + tg * 4 + pp;
        size_t pb = (size_t)py * WW + px;
#pragma unroll
        for (int j = 0; j < 4; j++) {
            float lo, hi;
            unpack2(acc[pp][j], lo, hi);
            int o0 = 2 * j, o1 = 2 * j + 1;
            out[(((size_t)(n * 8 + o0)) * CC + d) * HW + pb] = lo;
            out[(((size_t)(n * 8 + o1)) * CC + d) * HW + pb] = hi;
        }
    }
}

// ---------------- launcher ----------------
extern "C" void kernel_launch(void* const* d_in, const int* in_sizes, int n_in,
                              void* d_out, int out_size) {
    const float* x  = (const float*)d_in[0];
    const float* w1 = (const float*)d_in[1];
    const float* w2 = (const float*)d_in[2];
    const float* wl = (const float*)d_in[3];
    float* out = (float*)d_out;

    k1_stats<<<NB * TT * CC, 128>>>(x);                    // launch 1
    { dim3 g(4, NB * TT);  k3f_reduce<<<g, 1024>>>(x); }   // launch 2
    { dim3 g(16, NB * TT); k4f_gv<<<g, 256>>>(x, w1, w2); }// launch 3
    {
        int smem = (8 * PSZ + 1728 + 16) * 4;              // ~50.4 KB -> 4 CTAs/SM
        cudaFuncSetAttribute(k5_conv, cudaFuncAttributeMaxDynamicSharedMemorySize, smem);
        dim3 g(4, CC, NB);
        k5_conv<<<g, 256, smem>>>(wl, out);                // launch 4 (ncu-captured slot)
    }
}

// round 17
// speedup vs baseline: 1.5701x; 1.0212x over previous
#include <cuda_runtime.h>
#include <math.h>
#include <stdint.h>

#define NB 8
#define TT 8
#define CC 128
#define HH 64
#define WW 64
#define HW 4096

// ---------------- device scratch (no allocations allowed) ----------------
__device__ float g_M[NB * TT * CC];
__device__ int   g_imp[TT * CC];
__device__ float g_red[(size_t)NB * TT * 4 * HW];        // 4 MB
__device__ float g_gv[(size_t)NB * TT * CC * HW];        // 134 MB: gv = map[isel]*x

// ---------------- K1: M = mean_hw + max_hw ----------------
__global__ void k1_stats(const float* __restrict__ x) {
    int blk = blockIdx.x;
    const float* p = x + (size_t)blk * HW;
    float s = 0.f, m = -INFINITY;
    for (int i = threadIdx.x; i < HW; i += 128) {
        float v = p[i];
        s += v;
        m = fmaxf(m, v);
    }
    for (int o = 16; o; o >>= 1) {
        s += __shfl_down_sync(0xffffffffu, s, o);
        m = fmaxf(m, __shfl_down_sync(0xffffffffu, m, o));
    }
    __shared__ float ss[4], sm[4];
    int w = threadIdx.x >> 5, l = threadIdx.x & 31;
    if (l == 0) { ss[w] = s; sm[w] = m; }
    __syncthreads();
    if (threadIdx.x == 0) {
        float S = ss[0] + ss[1] + ss[2] + ss[3];
        float Mx = fmaxf(fmaxf(sm[0], sm[1]), fmaxf(sm[2], sm[3]));
        g_M[blk] = S * (1.f / (float)HW) + Mx;
    }
}

// ---------------- K3F: topk mask (per-block recompute) + masked channel reductions ----------------
__global__ void k3f_reduce(const float* __restrict__ x) {
    int nt = blockIdx.y;           // n*8+t
    int t = nt & 7;
    int tid = threadIdx.x;         // 1024 threads
    __shared__ float sM[NB * TT * CC];
    __shared__ int simp[CC];
    for (int i = tid; i < NB * TT * CC; i += 1024) sM[i] = g_M[i];
    __syncthreads();
    if (tid < CC) {
        int c = tid;
        int mch = 0, mtm = 0;
        for (int n = 0; n < NB; n++) {
            const float* row = &sM[(n * TT + t) * CC];
            float v = row[c];
            int cnt = 0;
            for (int c2 = 0; c2 < CC; c2++) {
                float u = row[c2];
                cnt += (u > v) || (u == v && c2 < c);
            }
            if (cnt < 64) mch = 1;
            int cntt = 0;
            for (int t2 = 0; t2 < TT; t2++) {
                float u = sM[(n * TT + t2) * CC + c];
                cntt += (u > v) || (u == v && t2 < t);
            }
            if (cntt < 4) mtm = 1;
        }
        int ip = mch ^ mtm;
        simp[c] = ip;
        g_imp[t * CC + c] = ip;   // duplicate writes across blocks: same value, benign
    }
    __syncthreads();

    int pix = blockIdx.x * 1024 + tid;   // grid.x = 4
    const float* p = x + (size_t)nt * CC * HW + pix;
    float s_all = 0.f, s_im = 0.f, mx_im = -INFINITY, mx_sub = -INFINITY;
#pragma unroll 4
    for (int c = 0; c < CC; c++) {
        float v = p[(size_t)c * HW];
        int ip = simp[c];
        float vi = ip ? v : 0.f;
        float vs = ip ? 0.f : v;
        s_all += v;
        s_im += vi;
        mx_im = fmaxf(mx_im, vi);
        mx_sub = fmaxf(mx_sub, vs);
    }
    float* r = g_red + (size_t)nt * 4 * HW + pix;
    r[0]          = s_im * (1.f / 64.f);
    r[HW]         = mx_im;
    r[2 * HW]     = (s_all - s_im) * (1.f / 64.f);
    r[3 * HW]     = mx_sub;
}

// ---------------- K4F: maps conv+sigmoid fused with gv = map*x ----------------
__global__ void k4f_gv(const float* __restrict__ x,
                       const float* __restrict__ w1, const float* __restrict__ w2) {
    int nt = blockIdx.y; int t = nt & 7;
    int pix = blockIdx.x * 256 + threadIdx.x;
    int y = pix >> 6, xq = pix & 63;
    __shared__ float sw1[18], sw2[18];
    __shared__ int simp[CC];
    if (threadIdx.x < 18) { sw1[threadIdx.x] = w1[threadIdx.x]; sw2[threadIdx.x] = w2[threadIdx.x]; }
    for (int i = threadIdx.x; i < CC; i += 256) simp[i] = g_imp[t * CC + i];
    __syncthreads();
    const float* r = g_red + (size_t)nt * 4 * HW;
    float a_im = 0.f, a_sub = 0.f;
#pragma unroll
    for (int kh = 0; kh < 3; kh++) {
        int gy = y + kh - 1;
        if (gy < 0 || gy >= HH) continue;
#pragma unroll
        for (int kw = 0; kw < 3; kw++) {
            int gx = xq + kw - 1;
            if (gx < 0 || gx >= WW) continue;
            int o = gy * WW + gx;
            a_im  += sw1[kh * 3 + kw] * r[o]          + sw1[9 + kh * 3 + kw] * r[HW + o];
            a_sub += sw2[kh * 3 + kw] * r[2 * HW + o] + sw2[9 + kh * 3 + kw] * r[3 * HW + o];
        }
    }
    float im = 1.f / (1.f + expf(-a_im));
    float sb = 1.f / (1.f + expf(-a_sub));

    const float* xp = x + (size_t)nt * CC * HW + pix;
    float* gp = g_gv + (size_t)nt * CC * HW + pix;
#pragma unroll 4
    for (int dd = 0; dd < CC; dd++) {
        float xv = xp[(size_t)dd * HW];
        float mv = simp[dd] ? im : sb;
        gp[(size_t)dd * HW] = mv * xv;
    }
}

// ---------------- K5: 3D conv on gv, half-set pipelined cp.async, 4 CTAs/SM ----------------
#define THY 32
#define THX 32
#define VROW 34
#define VCOL 40                    // [x0-4, x0+36) : 16B-aligned, halos free
#define PSZ (VROW * VCOL)          // 1360 floats per (t) plane
#define NCHK 10                    // float4 chunks per row

__device__ __forceinline__ unsigned long long pack2(float v) {
    unsigned long long r;
    asm("mov.b64 %0, {%1, %1};" : "=l"(r) : "f"(v));
    return r;
}
__device__ __forceinline__ void ffma2(unsigned long long& d, unsigned long long a, unsigned long long b) {
    asm("fma.rn.f32x2 %0, %1, %2, %0;" : "+l"(d) : "l"(a), "l"(b));
}
__device__ __forceinline__ void unpack2(unsigned long long v, float& lo, float& hi) {
    asm("mov.b64 {%0, %1}, %2;" : "=f"(lo), "=f"(hi) : "l"(v));
}
__device__ __forceinline__ void cp16(uint32_t dst, const void* src, bool ok) {
    int sz = ok ? 16 : 0;   // src-size 0 => full zero-fill
    asm volatile("cp.async.cg.shared.global [%0], [%1], 16, %2;" :: "r"(dst), "l"(src), "r"(sz));
}

extern __shared__ float smem5[];

__global__ void __launch_bounds__(256, 4) k5_conv(const float* __restrict__ wl,
                                                  float* __restrict__ out) {
    float* vs = smem5;               // 8 * PSZ floats; halves: A = planes t0-3, B = t4-7
    float* ws = vs + 8 * PSZ;        // 1728 floats: selected weights [kd][t][k9][o]

    int n = blockIdx.z;
    int d = blockIdx.y;
    int tileid = blockIdx.x;
    int y0 = (tileid >> 1) * THY, x0 = (tileid & 1) * THX;
    int tid = threadIdx.x;

    uint32_t vs_u32;
    {
        uint32_t a;
        asm("{ .reg .u64 t; cvta.to.shared.u64 t, %1; cvt.u32.u64 %0, t; }" : "=r"(a) : "l"(vs));
        vs_u32 = a;
    }

    // per-CTA selected weight staging: ws[((kd*8+t)*9+k9)*8+o] = wl[(o*16+isel)*27 + kd*9 + k9]
    for (int i = tid; i < 1728; i += 256) {
        int o = i & 7; int q = i >> 3;              // q in [0,216)
        int k9 = q % 9; int s = q / 9;              // s in [0,24)
        int t = s & 7, kd = s >> 3;
        int dd = d + kd - 1;
        int isel = (dd >= 0 && dd < CC) ? (g_imp[t * CC + dd] ? t : t + 8) : 0;
        ws[i] = wl[(o * 16 + isel) * 27 + kd * 9 + k9];
    }

    int kds[3], np = 0;
#pragma unroll
    for (int kd = 0; kd < 3; kd++) {
        int dd = d + kd - 1;
        if (dd >= 0 && dd < CC) kds[np++] = kd;
    }

    const float* gvn = g_gv + (size_t)n * TT * CC * HW;  // + (t*CC+dd)*HW

    // ---- phase-invariant staging slots: each thread serves 2 of 340 (row,chunk) slots ----
    int soff0, goff0, soff1 = 0, goff1 = 0;
    bool ok0, ok1, in1;
    {
        int e = tid;
        int row = e / NCHK, ch = e - row * NCHK;
        int gy = y0 + row - 1, gxs = x0 - 4 + ch * 4;
        ok0 = (gy >= 0 && gy < HH && gxs >= 0 && gxs + 4 <= WW);
        goff0 = ok0 ? (gy * WW + gxs) : 0;
        soff0 = (row * VCOL + ch * 4) * 4;
        e = tid + 256;
        in1 = (e < VROW * NCHK);
        if (in1) {
            row = e / NCHK; ch = e - row * NCHK;
            gy = y0 + row - 1; gxs = x0 - 4 + ch * 4;
            ok1 = (gy >= 0 && gy < HH && gxs >= 0 && gxs + 4 <= WW);
            goff1 = ok1 ? (gy * WW + gxs) : 0;
            soff1 = (row * VCOL + ch * 4) * 4;
        } else ok1 = false;
    }

    // stage one half-set (planes tbase..tbase+3) of phase dd; commits one group
    auto stage_half = [&](int tbase, int dd) {
        const float* gp = gvn + (size_t)dd * HW;
#pragma unroll
        for (int tt = 0; tt < 4; tt++) {
            int t = tbase + tt;
            const float* pb = gp + (size_t)t * CC * HW;
            uint32_t sb = vs_u32 + (uint32_t)(t * PSZ * 4);
            cp16(sb + soff0, pb + goff0, ok0);
            if (in1) cp16(sb + soff1, pb + goff1, ok1);
        }
        asm volatile("cp.async.commit_group;");
    };

    // compute 4 t-planes' contribution for phase kd
    int lx = tid & 31;
    int tg = tid >> 5;
    unsigned long long acc[4][4];
#pragma unroll
    for (int pp = 0; pp < 4; pp++)
#pragma unroll
        for (int j = 0; j < 4; j++) acc[pp][j] = 0ull;

    auto compute_half = [&](int tbase, int kd) {
        const float* vbase = vs + (tg * 4) * VCOL + (lx + 3);
        const float* wkd = ws + kd * 8 * 72;
        for (int tt = 0; tt < 4; tt++) {
            int t = tbase + tt;
            const float* wb = wkd + t * 72;
            const float* vb = vbase + t * PSZ;
#pragma unroll
            for (int kw = 0; kw < 3; kw++) {
                unsigned long long vp[6];
#pragma unroll
                for (int r = 0; r < 6; r++) vp[r] = pack2(vb[r * VCOL + kw]);
#pragma unroll
                for (int kh = 0; kh < 3; kh++) {
                    const ulonglong2* wq = (const ulonglong2*)(wb + (kh * 3 + kw) * 8);
                    ulonglong2 wA = wq[0], wB = wq[1];
#pragma unroll
                    for (int pp = 0; pp < 4; pp++) {
                        unsigned long long vv = vp[pp + kh];
                        ffma2(acc[pp][0], wA.x, vv);
                        ffma2(acc[pp][1], wA.y, vv);
                        ffma2(acc[pp][2], wB.x, vv);
                        ffma2(acc[pp][3], wB.y, vv);
                    }
                }
            }
        }
    };

    // prologue: stage both halves of phase 0 (groups: A0, B0)
    stage_half(0, d + kds[0] - 1);
    stage_half(4, d + kds[0] - 1);

    for (int i = 0; i < np; i++) {
        int kd = kds[i];
        bool more = (i + 1 < np);
        int ddn = more ? (d + kds[i + 1] - 1) : 0;

        // wait half A of phase i (FIFO: oldest pending group)
        asm volatile("cp.async.wait_group 1;");
        __syncthreads();            // A data (and ws on i==0) visible to all
        compute_half(0, kd);
        __syncthreads();            // all done reading half A
        if (more) stage_half(0, ddn);   // pending: B_i, A_{i+1}

        // wait half B of phase i
        if (more) asm volatile("cp.async.wait_group 1;");
        else      asm volatile("cp.async.wait_group 0;");
        __syncthreads();            // B data visible
        compute_half(4, kd);
        __syncthreads();            // all done reading half B
        if (more) stage_half(4, ddn);   // pending: A_{i+1}, B_{i+1}
    }

    int px = x0 + lx;
#pragma unroll
    for (int pp = 0; pp < 4; pp++) {
        int py = y0 + tg * 4 + pp;
        size_t pb = (size_t)py * WW + px;
#pragma unroll
        for (int j = 0; j < 4; j++) {
            float lo, hi;
            unpack2(acc[pp][j], lo, hi);
            int o0 = 2 * j, o1 = 2 * j + 1;
            out[(((size_t)(n * 8 + o0)) * CC + d) * HW + pb] = lo;
            out[(((size_t)(n * 8 + o1)) * CC + d) * HW + pb] = hi;
        }
    }
}

// ---------------- launcher ----------------
extern "C" void kernel_launch(void* const* d_in, const int* in_sizes, int n_in,
                              void* d_out, int out_size) {
    const float* x  = (const float*)d_in[0];
    const float* w1 = (const float*)d_in[1];
    const float* w2 = (const float*)d_in[2];
    const float* wl = (const float*)d_in[3];
    float* out = (float*)d_out;

    k1_stats<<<NB * TT * CC, 128>>>(x);                    // launch 1
    { dim3 g(4, NB * TT);  k3f_reduce<<<g, 1024>>>(x); }   // launch 2
    { dim3 g(16, NB * TT); k4f_gv<<<g, 256>>>(x, w1, w2); }// launch 3
    {
        int smem = (8 * PSZ + 1728 + 16) * 4;              // ~50.4 KB -> 4 CTAs/SM
        cudaFuncSetAttribute(k5_conv, cudaFuncAttributeMaxDynamicSharedMemorySize, smem);
        dim3 g(4, CC, NB);
        k5_conv<<<g, 256, smem>>>(wl, out);                // launch 4 (ncu-captured slot)
    }
}